// round 14
// baseline (speedup 1.0000x reference)
#include <cuda_runtime.h>
#include <cuda_bf16.h>
#include <cstdint>

#define BATCH   4
#define N1_PER  16384
#define N2_PER  4096
#define N1_TOT  (BATCH * N1_PER)
#define N2_TOT  (BATCH * N2_PER)
#define C_IN    512
#define C_OUT   256
#define BN_EPS  1e-5f
#define KT      4096

typedef unsigned long long ull;

// ---------------------------------------------------------------------------
// device-global scratch
// ---------------------------------------------------------------------------
__device__ float         g_h2[N2_TOT * C_OUT];
__device__ __nv_bfloat16 g_W1h[C_OUT * C_OUT];
__device__ __nv_bfloat16 g_W1l[C_OUT * C_OUT];
__device__ __nv_bfloat16 g_W2h[C_OUT * C_IN];
__device__ __nv_bfloat16 g_W2l[C_OUT * C_IN];
__device__ __nv_bfloat16 g_A1h[N1_TOT * C_OUT];
__device__ __nv_bfloat16 g_A1l[N1_TOT * C_OUT];
__device__ __nv_bfloat16 g_A2h[N2_TOT * C_IN];
__device__ __nv_bfloat16 g_A2l[N2_TOT * C_IN];
__device__ float         g_b1s[C_OUT];
__device__ float         g_b2s[C_OUT];
__device__ float         g_w3[N1_TOT * 3];
__device__ int           g_i3[N1_TOT * 3];

// ---------------------------------------------------------------------------
// helpers
// ---------------------------------------------------------------------------
__device__ __forceinline__ uint32_t smem_u32(const void* p) {
    uint32_t a;
    asm("{ .reg .u64 t; cvta.to.shared.u64 t, %1; cvt.u32.u64 %0, t; }"
        : "=r"(a) : "l"(p));
    return a;
}
__device__ __forceinline__ ull pack2(float lo, float hi) {
    ull r; asm("mov.b64 %0, {%1, %2};" : "=l"(r) : "f"(lo), "f"(hi)); return r;
}
__device__ __forceinline__ void unpack2(ull v, float& lo, float& hi) {
    asm("mov.b64 {%0, %1}, %2;" : "=f"(lo), "=f"(hi) : "l"(v));
}
__device__ __forceinline__ ull fma2(ull a, ull b, ull c) {
    ull r; asm("fma.rn.f32x2 %0, %1, %2, %3;" : "=l"(r) : "l"(a), "l"(b), "l"(c));
    return r;
}
__device__ __forceinline__ ull add2(ull a, ull b) {
    ull r; asm("add.rn.f32x2 %0, %1, %2;" : "=l"(r) : "l"(a), "l"(b)); return r;
}
__device__ __forceinline__ ull mul2(ull a, ull b) {
    ull r; asm("mul.rn.f32x2 %0, %1, %2;" : "=l"(r) : "l"(a), "l"(b)); return r;
}

// SW128 swizzle (Swizzle<3,4,3>)
__device__ __forceinline__ uint32_t sw128(uint32_t off) {
    return off ^ ((off >> 3) & 0x70);
}

#define LDSM4(r0, r1, r2, r3, addr) \
    asm volatile("ldmatrix.sync.aligned.m8n8.x4.shared.b16 {%0,%1,%2,%3}, [%4];" \
                 : "=r"(r0), "=r"(r1), "=r"(r2), "=r"(r3) : "r"(addr))

#define MMA_BF16(d, a0, a1, a2, a3, b0, b1) \
    asm volatile("mma.sync.aligned.m16n8k16.row.col.f32.bf16.bf16.f32 " \
                 "{%0,%1,%2,%3}, {%4,%5,%6,%7}, {%8,%9}, {%0,%1,%2,%3};" \
                 : "+f"((d)[0]), "+f"((d)[1]), "+f"((d)[2]), "+f"((d)[3]) \
                 : "r"(a0), "r"(a1), "r"(a2), "r"(a3), "r"(b0), "r"(b1))

#define CP_ASYNC16(saddr, gptr) \
    asm volatile("cp.async.cg.shared.global [%0], [%1], 16;" \
                 :: "r"(saddr), "l"(gptr) : "memory")
#define CP_COMMIT() asm volatile("cp.async.commit_group;" ::: "memory")
#define CP_WAIT(n)  asm volatile("cp.async.wait_group %0;" :: "n"(n) : "memory")

// ---------------------------------------------------------------------------
// prep: fold BN into weights, split into bf16 hi/lo ([N][K] row-major)
// ---------------------------------------------------------------------------
__global__ void prep_weights(const float* __restrict__ W1, const float* __restrict__ b1,
                             const float* __restrict__ g1, const float* __restrict__ be1,
                             const float* __restrict__ m1, const float* __restrict__ v1,
                             const float* __restrict__ W2, const float* __restrict__ b2,
                             const float* __restrict__ g2, const float* __restrict__ be2,
                             const float* __restrict__ m2, const float* __restrict__ v2)
{
    int n = blockIdx.x;
    float s1 = g1[n] * rsqrtf(v1[n] + BN_EPS);
    float s2 = g2[n] * rsqrtf(v2[n] + BN_EPS);
    for (int k = threadIdx.x; k < C_OUT; k += blockDim.x) {
        float w = W1[n * C_OUT + k] * s1;
        uint32_t hb = __float_as_uint(w) & 0xFFFF0000u;
        g_W1h[n * C_OUT + k] = __ushort_as_bfloat16((unsigned short)(hb >> 16));
        g_W1l[n * C_OUT + k] = __float2bfloat16(w - __uint_as_float(hb));
    }
    for (int k = threadIdx.x; k < C_IN; k += blockDim.x) {
        float w = W2[n * C_IN + k] * s2;
        uint32_t hb = __float_as_uint(w) & 0xFFFF0000u;
        g_W2h[n * C_IN + k] = __ushort_as_bfloat16((unsigned short)(hb >> 16));
        g_W2l[n * C_IN + k] = __float2bfloat16(w - __uint_as_float(hb));
    }
    if (threadIdx.x == 0) {
        g_b1s[n] = (b1[n] - m1[n]) * s1 + be1[n];
        g_b2s[n] = (b2[n] - m2[n]) * s2 + be2[n];
    }
}

// ---------------------------------------------------------------------------
// A pre-convert: fp32 -> bf16 hi (truncate) / lo (rn residual)
// ---------------------------------------------------------------------------
template <int LAYER>
__global__ __launch_bounds__(256)
void conv_A(const float* __restrict__ src, int n4)
{
    __nv_bfloat16* __restrict__ Hi = (LAYER == 1) ? g_A1h : g_A2h;
    __nv_bfloat16* __restrict__ Lo = (LAYER == 1) ? g_A1l : g_A2l;
    int idx = blockIdx.x * 256 + threadIdx.x;
    if (idx >= n4) return;
    float4 v = ((const float4*)src)[idx];
    float e[4] = {v.x, v.y, v.z, v.w};
    uint32_t hi[2], lo[2];
#pragma unroll
    for (int p = 0; p < 2; p++) {
        uint32_t b0 = __float_as_uint(e[2 * p])     & 0xFFFF0000u;
        uint32_t b1 = __float_as_uint(e[2 * p + 1]) & 0xFFFF0000u;
        float l0 = e[2 * p]     - __uint_as_float(b0);
        float l1 = e[2 * p + 1] - __uint_as_float(b1);
        hi[p] = (b0 >> 16) | b1;
        asm("cvt.rn.bf16x2.f32 %0, %1, %2;" : "=r"(lo[p]) : "f"(l1), "f"(l0));
    }
    ((uint2*)Hi)[idx] = make_uint2(hi[0], hi[1]);
    ((uint2*)Lo)[idx] = make_uint2(lo[0], lo[1]);
}

// ---------------------------------------------------------------------------
// mma.sync bf16 GEMM, 3-term hi/lo split, cp.async 2-stage pipeline.
// CTA tile 128x128 (grid x=N/128, y=M/128), 256 thr = 8 warps (2x4),
// warp tile 64x32, K chunks of 64 in SW128-swizzled smem.
// smem: 2 stages x (Ah|Al|Bh|Bl 16KB each) = 128 KB; epilogue reuses as
// float[128][132]. LAYER==1 epilogue also fuses the kNN gather-add:
// out = relu(gemm+bias) + sum_k w_k * h2[idx_k] (gemm2 + knn ran before).
// ---------------------------------------------------------------------------
#define SM_AH 0
#define SM_AL 16384
#define SM_BH 32768
#define SM_BL 49152
#define STAGE_BYTES 65536
#define EPSTR 132
#define GEMM_SMEM (2 * STAGE_BYTES)   // 131072

template <int KTOT, int LAYER>
__global__ __launch_bounds__(256)
void gemm_mma(float* __restrict__ Cout)
{
    extern __shared__ __align__(1024) char dsm[];

    const __nv_bfloat16* __restrict__ Ah = (LAYER == 1) ? g_A1h : g_A2h;
    const __nv_bfloat16* __restrict__ Al = (LAYER == 1) ? g_A1l : g_A2l;
    const __nv_bfloat16* __restrict__ Wh = (LAYER == 1) ? g_W1h : g_W2h;
    const __nv_bfloat16* __restrict__ Wl = (LAYER == 1) ? g_W1l : g_W2l;
    const float* __restrict__ bias       = (LAYER == 1) ? g_b1s : g_b2s;
    float* __restrict__ C                = (LAYER == 1) ? Cout  : g_h2;

    const int tid = threadIdx.x;
    const int wid = tid >> 5;
    const int lid = tid & 31;
    const int wm  = wid & 1;
    const int wn  = wid >> 1;
    const int bn  = blockIdx.x;
    const int bm  = blockIdx.y;

    const uint32_t sb = smem_u32(dsm);
    const __nv_bfloat16* AhB = Ah + (size_t)bm * 128 * KTOT;
    const __nv_bfloat16* AlB = Al + (size_t)bm * 128 * KTOT;
    const __nv_bfloat16* WhB = Wh + (size_t)bn * 128 * KTOT;
    const __nv_bfloat16* WlB = Wl + (size_t)bn * 128 * KTOT;

    const int NCH = KTOT / 64;

    float acc[4][4][4];
#pragma unroll
    for (int i = 0; i < 4; i++)
#pragma unroll
        for (int j = 0; j < 4; j++)
#pragma unroll
            for (int f = 0; f < 4; f++) acc[i][j][f] = 0.f;

    const int lrow = lid & 15;
    const int lkb  = (lid >> 4) * 16;

#define STAGE_CHUNK(c, buf)                                                     \
    do {                                                                        \
        uint32_t sbase = sb + (uint32_t)(buf) * STAGE_BYTES;                    \
        _Pragma("unroll")                                                       \
        for (int i = 0; i < 4; i++) {                                           \
            int u = tid + i * 256;                                              \
            int row = u >> 3, seg = u & 7;                                      \
            uint32_t off = sw128((uint32_t)row * 128u + (uint32_t)seg * 16u);   \
            size_t goff = (size_t)row * KTOT + (c) * 64 + seg * 8;              \
            CP_ASYNC16(sbase + SM_AH + off, AhB + goff);                        \
            CP_ASYNC16(sbase + SM_AL + off, AlB + goff);                        \
            CP_ASYNC16(sbase + SM_BH + off, WhB + goff);                        \
            CP_ASYNC16(sbase + SM_BL + off, WlB + goff);                        \
        }                                                                       \
        CP_COMMIT();                                                            \
    } while (0)

    STAGE_CHUNK(0, 0);

    for (int c = 0; c < NCH; c++) {
        const int buf = c & 1;
        if (c + 1 < NCH) {
            STAGE_CHUNK(c + 1, buf ^ 1);
            CP_WAIT(1);
        } else {
            CP_WAIT(0);
        }
        __syncthreads();

        const uint32_t sbase = sb + (uint32_t)buf * STAGE_BYTES;
#pragma unroll
        for (int kk = 0; kk < 4; kk++) {
            uint32_t ah[4][4], al[4][4], bh[4][2], bl[4][2];
#pragma unroll
            for (int mi = 0; mi < 4; mi++) {
                uint32_t row = (uint32_t)(wm * 64 + mi * 16 + lrow);
                uint32_t adr = sw128(row * 128u + (uint32_t)(kk * 32 + lkb));
                LDSM4(ah[mi][0], ah[mi][1], ah[mi][2], ah[mi][3], sbase + SM_AH + adr);
                LDSM4(al[mi][0], al[mi][1], al[mi][2], al[mi][3], sbase + SM_AL + adr);
            }
#pragma unroll
            for (int nj = 0; nj < 2; nj++) {
                uint32_t row = (uint32_t)(wn * 32 + nj * 16 + lrow);
                uint32_t adr = sw128(row * 128u + (uint32_t)(kk * 32 + lkb));
                uint32_t r0, r1, r2, r3;
                LDSM4(r0, r1, r2, r3, sbase + SM_BH + adr);
                bh[2 * nj][0] = r0; bh[2 * nj][1] = r2;
                bh[2 * nj + 1][0] = r1; bh[2 * nj + 1][1] = r3;
                LDSM4(r0, r1, r2, r3, sbase + SM_BL + adr);
                bl[2 * nj][0] = r0; bl[2 * nj][1] = r2;
                bl[2 * nj + 1][0] = r1; bl[2 * nj + 1][1] = r3;
            }
#pragma unroll
            for (int mi = 0; mi < 4; mi++)
#pragma unroll
                for (int ni = 0; ni < 4; ni++) {
                    MMA_BF16(acc[mi][ni], ah[mi][0], ah[mi][1], ah[mi][2], ah[mi][3],
                             bh[ni][0], bh[ni][1]);
                    MMA_BF16(acc[mi][ni], al[mi][0], al[mi][1], al[mi][2], al[mi][3],
                             bh[ni][0], bh[ni][1]);
                    MMA_BF16(acc[mi][ni], ah[mi][0], ah[mi][1], ah[mi][2], ah[mi][3],
                             bl[ni][0], bl[ni][1]);
                }
        }
        __syncthreads();
    }

    // ---- epilogue: frags -> smem -> bias+relu (+fused gather) -> global ----
    float* Cs = (float*)dsm;
    const int frow = lid >> 2;
    const int fcol = (lid & 3) * 2;
#pragma unroll
    for (int mi = 0; mi < 4; mi++)
#pragma unroll
        for (int ni = 0; ni < 4; ni++) {
            int r0 = wm * 64 + mi * 16 + frow;
            int cc = wn * 32 + ni * 8 + fcol;
            Cs[(size_t)r0 * EPSTR + cc]           = acc[mi][ni][0];
            Cs[(size_t)r0 * EPSTR + cc + 1]       = acc[mi][ni][1];
            Cs[(size_t)(r0 + 8) * EPSTR + cc]     = acc[mi][ni][2];
            Cs[(size_t)(r0 + 8) * EPSTR + cc + 1] = acc[mi][ni][3];
        }
    __syncthreads();
#pragma unroll
    for (int i = 0; i < 16; i++) {
        int idx = tid + i * 256;
        int row = idx >> 5, c4 = idx & 31;
        float4 v = *(const float4*)&Cs[(size_t)row * EPSTR + c4 * 4];
        float4 bv = *(const float4*)&bias[bn * 128 + c4 * 4];
        v.x = fmaxf(v.x + bv.x, 0.f);
        v.y = fmaxf(v.y + bv.y, 0.f);
        v.z = fmaxf(v.z + bv.z, 0.f);
        v.w = fmaxf(v.w + bv.w, 0.f);
        if (LAYER == 1) {
            // fused kNN interpolation add (h2 + knn results are ready)
            int gq = bm * 128 + row;
            float w0 = g_w3[gq * 3 + 0];
            float w1 = g_w3[gq * 3 + 1];
            float w2 = g_w3[gq * 3 + 2];
            int   r0 = g_i3[gq * 3 + 0];
            int   r1 = g_i3[gq * 3 + 1];
            int   r2 = g_i3[gq * 3 + 2];
            size_t coff = (size_t)bn * 128 + c4 * 4;
            float4 f0 = *(const float4*)(g_h2 + (size_t)r0 * C_OUT + coff);
            float4 f1 = *(const float4*)(g_h2 + (size_t)r1 * C_OUT + coff);
            float4 f2 = *(const float4*)(g_h2 + (size_t)r2 * C_OUT + coff);
            v.x += w0 * f0.x + w1 * f1.x + w2 * f2.x;
            v.y += w0 * f0.y + w1 * f1.y + w2 * f2.y;
            v.z += w0 * f0.z + w1 * f1.z + w2 * f2.z;
            v.w += w0 * f0.w + w1 * f1.w + w2 * f2.w;
        }
        *((float4*)(C + (size_t)(bm * 128 + row) * C_OUT + bn * 128) + c4) = v;
    }
#undef STAGE_CHUNK
}

// ---------------------------------------------------------------------------
// top-3 update (caller guarantees d < d2)
// ---------------------------------------------------------------------------
__device__ __forceinline__ void upd3(float d, int j,
                                     float& d0, float& d1, float& d2,
                                     int& i0, int& i1, int& i2)
{
    if (d < d1) {
        d2 = d1; i2 = i1;
        if (d < d0) { d1 = d0; i1 = i0; d0 = d; i0 = j; }
        else        { d1 = d;  i1 = j; }
    } else { d2 = d; i2 = j; }
}

// ---------------------------------------------------------------------------
// 3-NN: exact d^2 in packed f32x2. Support staged as PRE-PACKED 64-bit pairs
// (ulonglong2 LDS.128 -> halves are ready f32x2 operands; zero pack MOVs).
// 256 thr/block (1 query/thread), 256 blocks, 48KB smem -> 8 warps x 4 CTAs.
// ---------------------------------------------------------------------------
__global__ __launch_bounds__(256)
void knn_search(const float* __restrict__ p1, const float* __restrict__ p2)
{
    __shared__ ull sX[KT / 2];   // 16 KB each: pair j = pts (2j, 2j+1)
    __shared__ ull sY[KT / 2];
    __shared__ ull sZ[KT / 2];

    const int b    = blockIdx.x >> 6;    // 64 blocks per batch
    const int qblk = blockIdx.x & 63;
    const int tid  = threadIdx.x;

    const float* src = p2 + (size_t)b * KT * 3;
    for (int pt = tid; pt < KT; pt += 256) {
        ((float*)sX)[pt] = src[pt * 3 + 0];
        ((float*)sY)[pt] = src[pt * 3 + 1];
        ((float*)sZ)[pt] = src[pt * 3 + 2];
    }
    __syncthreads();

    const int q = b * N1_PER + qblk * 256 + tid;
    const float qx = p1[q * 3 + 0];
    const float qy = p1[q * 3 + 1];
    const float qz = p1[q * 3 + 2];
    const ull nqx = pack2(-qx, -qx);
    const ull nqy = pack2(-qy, -qy);
    const ull nqz = pack2(-qz, -qz);

    float d0 = 1e30f, d1 = 1e30f, d2 = 1e30f;
    int   i0 = 0,     i1 = 0,     i2 = 0;

    const ulonglong2* pX = (const ulonglong2*)sX;
    const ulonglong2* pY = (const ulonglong2*)sY;
    const ulonglong2* pZ = (const ulonglong2*)sZ;

    for (int g = 0; g < KT / 16; g++) {
        float r[16];
#pragma unroll
        for (int p = 0; p < 4; p++) {
            ulonglong2 X = pX[g * 4 + p];
            ulonglong2 Y = pY[g * 4 + p];
            ulonglong2 Z = pZ[g * 4 + p];
            ull dxa = add2(X.x, nqx);
            ull dya = add2(Y.x, nqy);
            ull dza = add2(Z.x, nqz);
            ull da  = fma2(dza, dza, fma2(dya, dya, mul2(dxa, dxa)));
            ull dxb = add2(X.y, nqx);
            ull dyb = add2(Y.y, nqy);
            ull dzb = add2(Z.y, nqz);
            ull db  = fma2(dzb, dzb, fma2(dyb, dyb, mul2(dxb, dxb)));
            unpack2(da, r[4 * p + 0], r[4 * p + 1]);
            unpack2(db, r[4 * p + 2], r[4 * p + 3]);
        }
        float m0 = fminf(r[0],  r[1]);
        float m1 = fminf(r[2],  r[3]);
        float m2 = fminf(r[4],  r[5]);
        float m3 = fminf(r[6],  r[7]);
        float m4 = fminf(r[8],  r[9]);
        float m5 = fminf(r[10], r[11]);
        float m6 = fminf(r[12], r[13]);
        float m7 = fminf(r[14], r[15]);
        float m = fminf(fminf(fminf(m0, m1), fminf(m2, m3)),
                        fminf(fminf(m4, m5), fminf(m6, m7)));
        if (m < d2) {
            const int base = g * 16;
#pragma unroll
            for (int cidx = 0; cidx < 16; cidx++)
                if (r[cidx] < d2)
                    upd3(r[cidx], base + cidx, d0, d1, d2, i0, i1, i2);
        }
    }

    float s0 = sqrtf(fmaxf(d0, 1e-12f));
    float s1 = sqrtf(fmaxf(d1, 1e-12f));
    float s2 = sqrtf(fmaxf(d2, 1e-12f));
    float w0 = 1.f / (s0 + 1e-8f);
    float w1 = 1.f / (s1 + 1e-8f);
    float w2 = 1.f / (s2 + 1e-8f);
    float inv = 1.f / (w0 + w1 + w2);

    g_w3[q * 3 + 0] = w0 * inv;
    g_w3[q * 3 + 1] = w1 * inv;
    g_w3[q * 3 + 2] = w2 * inv;
    g_i3[q * 3 + 0] = b * N2_PER + i0;
    g_i3[q * 3 + 1] = b * N2_PER + i1;
    g_i3[q * 3 + 2] = b * N2_PER + i2;
}

// ---------------------------------------------------------------------------
extern "C" void kernel_launch(void* const* d_in, const int* in_sizes, int n_in,
                              void* d_out, int out_size)
{
    const float* p1 = (const float*)d_in[0];
    const float* x1 = (const float*)d_in[1];
    const float* p2 = (const float*)d_in[2];
    const float* x2 = (const float*)d_in[3];

    cudaFuncSetAttribute(gemm_mma<C_OUT, 1>,
                         cudaFuncAttributeMaxDynamicSharedMemorySize, GEMM_SMEM);
    cudaFuncSetAttribute(gemm_mma<C_IN, 2>,
                         cudaFuncAttributeMaxDynamicSharedMemorySize, GEMM_SMEM);

    prep_weights<<<C_OUT, 256>>>((const float*)d_in[4],  (const float*)d_in[5],
                                 (const float*)d_in[6],  (const float*)d_in[7],
                                 (const float*)d_in[8],  (const float*)d_in[9],
                                 (const float*)d_in[10], (const float*)d_in[11],
                                 (const float*)d_in[12], (const float*)d_in[13],
                                 (const float*)d_in[14], (const float*)d_in[15]);
    conv_A<2><<<(N2_TOT * C_IN / 4 + 255) / 256, 256>>>(x2, N2_TOT * C_IN / 4);
    conv_A<1><<<(N1_TOT * C_OUT / 4 + 255) / 256, 256>>>(x1, N1_TOT * C_OUT / 4);

    {   // h2 = relu(bn(x2 @ W2^T)) -> g_h2
        dim3 grid(C_OUT / 128, N2_TOT / 128);
        gemm_mma<C_IN, 2><<<grid, 256, GEMM_SMEM>>>(nullptr);
    }
    // kNN (needs nothing from GEMMs; must precede gemm1's fused gather)
    knn_search<<<BATCH * (N1_PER / 256), 256>>>(p1, p2);

    {   // out = relu(bn(x1 @ W1^T)) + interp(h2)  -> d_out (fused epilogue)
        dim3 grid(C_OUT / 128, N1_TOT / 128);
        gemm_mma<C_OUT, 1><<<grid, 256, GEMM_SMEM>>>((float*)d_out);
    }
}